// round 3
// baseline (speedup 1.0000x reference)
#include <cuda_runtime.h>
#include <math.h>

#define N_PTS   32768
#define KCODES  2048
#define DIM     128
#define BM      128
#define BN      64
#define NTILES  (KCODES / BN)        // 32
#define TEMP_INV (1.0f/0.9f)

// Scratch (allocation-free rule: __device__ globals)
__device__ float g_conf[(size_t)N_PTS * KCODES];   // 256 MB conf' spill
__device__ float g_maxv[N_PTS];
__device__ float g_esq[KCODES];
__device__ float g_clsum[KCODES];
__device__ float g_bhi[KCODES * DIM];              // B hi split, fragment order
__device__ float g_blo[KCODES * DIM];              // B lo split, fragment order

__device__ __forceinline__ float tf32r(float a) {
    float r;
    asm("cvt.rna.tf32.f32 %0, %1;" : "=f"(r) : "f"(a));
    return r;
}

#define MMA_TF32(d, a, b) \
    asm volatile("mma.sync.aligned.m16n8k8.row.col.f32.tf32.tf32.f32 " \
        "{%0,%1,%2,%3},{%4,%5,%6,%7},{%8,%9},{%0,%1,%2,%3};" \
        : "+f"((d)[0]), "+f"((d)[1]), "+f"((d)[2]), "+f"((d)[3]) \
        : "r"(__float_as_uint((a)[0])), "r"(__float_as_uint((a)[1])), \
          "r"(__float_as_uint((a)[2])), "r"(__float_as_uint((a)[3])), \
          "r"(__float_as_uint((b)[0])), "r"(__float_as_uint((b)[1])))

// ---------------------------------------------------------------------------
// Kernel 1: e_sq per code (warp per code), zero class accumulators, and
// pre-split embed into tf32 hi/lo IN MMA FRAGMENT ORDER:
//   g_b*[ ((((ct*2+wn)*4+nt)*16 + ks)*32 + gid*4 + tig)*2 + slot ]
// grid 256 x 256 = 65536 threads: warp per code (esq) + float4 per thread (split)
// ---------------------------------------------------------------------------
__global__ void prep_kernel(const float* __restrict__ embed) {
    const int tid  = blockIdx.x * blockDim.x + threadIdx.x;  // 0..65535
    const int lane = tid & 31;
    const int warp = tid >> 5;
    if (tid < KCODES) g_clsum[tid] = 0.f;

    // e_sq
    {
        const float* row = embed + (size_t)warp * DIM;
        float s = 0.f;
        #pragma unroll
        for (int i = 0; i < 4; ++i) { float v = row[lane + 32 * i]; s = fmaf(v, v, s); }
        #pragma unroll
        for (int o = 16; o > 0; o >>= 1) s += __shfl_down_sync(0xffffffffu, s, o);
        if (lane == 0) g_esq[warp] = s;
    }

    // B split: one float4 (4 consecutive k) per thread
    {
        float4 v = ((const float4*)embed)[tid];
        const int n  = tid >> 5;           // code row
        const int k4 = tid & 31;           // float4 index along k
        const int ct = n >> 6;
        const int wn = (n >> 5) & 1;
        const int nt = (n >> 3) & 3;
        const int gid = n & 7;
        const int ks = k4 >> 1;
        const int slot = k4 & 1;
        float a4[4] = {v.x, v.y, v.z, v.w};
        #pragma unroll
        for (int j = 0; j < 4; ++j) {
            float hi = tf32r(a4[j]);
            float lo = tf32r(a4[j] - hi);
            size_t o = ((size_t)((((ct * 2 + wn) * 4 + nt) * 16 + ks) * 32) + gid * 4 + j) * 2 + slot;
            g_bhi[o] = hi;
            g_blo[o] = lo;
        }
    }
}

// ---------------------------------------------------------------------------
// Kernel 2: 3xTF32 GEMM with fragment-order smem operands.
// smem: a_hi[16384] a_lo[16384] (fragment order, 128KB)
//       b_hi[8192]  b_lo[8192]  (fragment order, 64KB) -> 192KB total
// 8 warps (4m x 2n), warp tile 32x32, K=128 resident, 32 B-tiles of 64 codes.
// B tiles register-prefetched one tile ahead from pre-split global arrays.
// ---------------------------------------------------------------------------
__global__ void __launch_bounds__(256, 1)
gemm_kernel(const float* __restrict__ x,
            const float* __restrict__ embed,
            float* __restrict__ out_q,
            float* __restrict__ out_ind) {
    extern __shared__ float sm[];
    float* a_hi = sm;
    float* a_lo = sm + 16384;
    float* b_hi = sm + 32768;
    float* b_lo = sm + 40960;

    const int tid  = threadIdx.x;
    const int lane = tid & 31;
    const int w    = tid >> 5;
    const int wm   = w >> 1;          // 0..3: 32-point slab
    const int wn   = w & 1;           // 0..1: 32-code slab
    const int n0   = blockIdx.x * BM;

    // ---- A split (x scaled by 2, exact) directly into fragment order ----
    {
        const float4* x4 = (const float4*)(x + (size_t)n0 * DIM);
        #pragma unroll
        for (int t = 0; t < 16; ++t) {
            int idx = t * 256 + tid;
            int m  = idx >> 5;
            int k4 = idx & 31;
            float4 v = x4[idx];
            float a4[4] = {2.f * v.x, 2.f * v.y, 2.f * v.z, 2.f * v.w};
            int r    = m & 15;
            int base = ((((m >> 5) * 2 + ((m >> 4) & 1)) * 16 + (k4 >> 1)) * 32) * 4;
            int sl   = (r >> 3) + ((k4 & 1) << 1);
            #pragma unroll
            for (int j = 0; j < 4; ++j) {
                float hi = tf32r(a4[j]);
                float lo = tf32r(a4[j] - hi);
                int addr = base + ((r & 7) * 4 + j) * 4 + sl;
                a_hi[addr] = hi;
                a_lo[addr] = lo;
            }
        }
    }

    // ---- B tile 0: direct copy from pre-split global fragments ----
    const float4* gbh4 = (const float4*)g_bhi;
    const float4* gbl4 = (const float4*)g_blo;
    float4* sbh4 = (float4*)b_hi;
    float4* sbl4 = (float4*)b_lo;
    #pragma unroll
    for (int i = 0; i < 8; ++i) {
        sbh4[i * 256 + tid] = gbh4[i * 256 + tid];
        sbl4[i * 256 + tid] = gbl4[i * 256 + tid];
    }

    float runv[4];
    int   runi[4];
    #pragma unroll
    for (int i = 0; i < 4; ++i) { runv[i] = -3.0e38f; runi[i] = 0; }

    float4 pfh[8], pfl[8];

    for (int ct = 0; ct < NTILES; ++ct) {
        const int c0 = ct * BN;
        __syncthreads();                      // B tile ct ready in smem

        // prefetch next tile into registers (L2-resident, hidden under MMAs)
        if (ct + 1 < NTILES) {
            #pragma unroll
            for (int i = 0; i < 8; ++i) {
                pfh[i] = gbh4[(ct + 1) * 2048 + i * 256 + tid];
                pfl[i] = gbl4[(ct + 1) * 2048 + i * 256 + tid];
            }
        }

        float acc[2][4][4];
        #pragma unroll
        for (int mt = 0; mt < 2; ++mt)
            #pragma unroll
            for (int nt = 0; nt < 4; ++nt)
                #pragma unroll
                for (int r = 0; r < 4; ++r) acc[mt][nt][r] = 0.f;

        #pragma unroll
        for (int ks = 0; ks < 16; ++ks) {
            float4 ah4[2], al4[2];
            #pragma unroll
            for (int mt = 0; mt < 2; ++mt) {
                int ab = (((wm * 2 + mt) * 16 + ks) * 32 + lane) * 4;
                ah4[mt] = *(const float4*)&a_hi[ab];
                al4[mt] = *(const float4*)&a_lo[ab];
            }
            float2 bh2[4], bl2[4];
            #pragma unroll
            for (int nt = 0; nt < 4; ++nt) {
                int bb = (((wn * 4 + nt) * 16 + ks) * 32 + lane) * 2;
                bh2[nt] = *(const float2*)&b_hi[bb];
                bl2[nt] = *(const float2*)&b_lo[bb];
            }
            #pragma unroll
            for (int mt = 0; mt < 2; ++mt)
                #pragma unroll
                for (int nt = 0; nt < 4; ++nt) {
                    MMA_TF32(acc[mt][nt], (&ah4[mt].x), (&bh2[nt].x));   // hi*hi
                    MMA_TF32(acc[mt][nt], (&ah4[mt].x), (&bl2[nt].x));   // hi*lo
                    MMA_TF32(acc[mt][nt], (&al4[mt].x), (&bh2[nt].x));   // lo*hi
                }
        }

        __syncthreads();                      // all warps done reading B smem
        if (ct + 1 < NTILES) {
            #pragma unroll
            for (int i = 0; i < 8; ++i) {
                sbh4[i * 256 + tid] = pfh[i];
                sbl4[i * 256 + tid] = pfl[i];
            }
        }

        // ---- epilogue: conf = acc - esq, argmax (ascending code), spill ----
        #pragma unroll
        for (int nt = 0; nt < 4; ++nt) {
            int cb = c0 + wn * 32 + nt * 8 + 2 * (lane & 3);
            float e0 = __ldg(&g_esq[cb]);
            float e1 = __ldg(&g_esq[cb + 1]);
            #pragma unroll
            for (int mt = 0; mt < 2; ++mt) {
                #pragma unroll
                for (int h = 0; h < 2; ++h) {
                    int slot = mt * 2 + h;
                    int row  = n0 + wm * 32 + mt * 16 + (lane >> 2) + h * 8;
                    float v0 = acc[mt][nt][2 * h + 0] - e0;
                    float v1 = acc[mt][nt][2 * h + 1] - e1;
                    if (v0 > runv[slot]) { runv[slot] = v0; runi[slot] = cb; }
                    if (v1 > runv[slot]) { runv[slot] = v1; runi[slot] = cb + 1; }
                    *(float2*)&g_conf[(size_t)row * KCODES + cb] = make_float2(v0, v1);
                }
            }
        }
    }

    // ---- cross-thread argmax reduction: 8 contributors per point row ----
    __syncthreads();
    float* red_v = sm;                         // [BM][8]
    int*   red_i = (int*)(sm + BM * 8);        // [BM][8]
    int*   sidx  = (int*)(sm + BM * 16);       // [BM]
    #pragma unroll
    for (int mt = 0; mt < 2; ++mt)
        #pragma unroll
        for (int h = 0; h < 2; ++h) {
            int slot = mt * 2 + h;
            int rloc = wm * 32 + mt * 16 + (lane >> 2) + h * 8;
            int cidx = wn * 4 + (lane & 3);
            red_v[rloc * 8 + cidx] = runv[slot];
            red_i[rloc * 8 + cidx] = runi[slot];
        }
    __syncthreads();
    if (tid < BM) {
        float bv = red_v[tid * 8];
        int   bi = red_i[tid * 8];
        #pragma unroll
        for (int t = 1; t < 8; ++t) {
            float v  = red_v[tid * 8 + t];
            int   ii = red_i[tid * 8 + t];
            if (v > bv || (v == bv && ii < bi)) { bv = v; bi = ii; }
        }
        g_maxv[n0 + tid]  = bv;
        sidx[tid]         = bi;
        out_ind[n0 + tid] = (float)bi;
    }
    __syncthreads();

    // ---- fused gather: one warp copies one 512B codebook row per point ----
    {
        const float4* e4 = (const float4*)embed;
        float4*       q4 = (float4*)out_q;
        for (int p = w; p < BM; p += 8) {
            int idx = sidx[p];
            q4[(size_t)(n0 + p) * 32 + lane] = e4[(size_t)idx * 32 + lane];
        }
    }
}

// ---------------------------------------------------------------------------
// Kernel 3: softmax v2 - persistent blocks, smem class bins, no skip branch.
// 8 points per group (warp per point); bins owned per-thread (k = tid mod 256),
// flushed once per block with a global atomic.
// ---------------------------------------------------------------------------
__global__ void softmax_kernel() {
    extern __shared__ float smem[];
    float* eb   = smem;                        // [8][KCODES]
    float* bins = smem + 8 * KCODES;           // [KCODES]
    float* zinv = bins + KCODES;               // [8]
    const int tid  = threadIdx.x;
    const int lane = tid & 31;
    const int w    = tid >> 5;

    for (int k = tid; k < KCODES; k += 256) bins[k] = 0.f;

    for (int g = blockIdx.x; g < N_PTS / 8; g += gridDim.x) {
        const int n = g * 8 + w;
        const float m = g_maxv[n];
        const float4* row4 = (const float4*)&g_conf[(size_t)n * KCODES];

        float z = 0.f;
        #pragma unroll
        for (int j = 0; j < 16; ++j) {
            int k4 = j * 32 + lane;
            float4 c = row4[k4];
            float4 e;
            e.x = __expf((c.x - m) * TEMP_INV);
            e.y = __expf((c.y - m) * TEMP_INV);
            e.z = __expf((c.z - m) * TEMP_INV);
            e.w = __expf((c.w - m) * TEMP_INV);
            *(float4*)&eb[w * KCODES + k4 * 4] = e;
            z += (e.x + e.y) + (e.z + e.w);
        }
        #pragma unroll
        for (int o = 16; o > 0; o >>= 1) z += __shfl_down_sync(0xffffffffu, z, o);
        if (lane == 0) zinv[w] = 1.f / z;      // z >= 1 (argmax term)
        __syncthreads();

        for (int k = tid; k < KCODES; k += 256) {
            float s = 0.f;
            #pragma unroll
            for (int ww = 0; ww < 8; ++ww) s = fmaf(eb[ww * KCODES + k], zinv[ww], s);
            bins[k] += s;
        }
        __syncthreads();
    }

    for (int k = tid; k < KCODES; k += 256) atomicAdd(&g_clsum[k], bins[k]);
}

// ---------------------------------------------------------------------------
// Kernel 4: diversity loss = sum_k p_k * log(p_k + eps).
// ---------------------------------------------------------------------------
__global__ void loss_kernel(float* __restrict__ out_loss) {
    __shared__ float red[256];
    const int tid = threadIdx.x;
    float acc = 0.f;
    for (int k = tid; k < KCODES; k += 256) {
        float p = g_clsum[k] * (1.0f / (float)N_PTS);
        acc += p * logf(p + 1e-6f);
    }
    red[tid] = acc;
    __syncthreads();
    for (int s = 128; s > 0; s >>= 1) {
        if (tid < s) red[tid] += red[tid + s];
        __syncthreads();
    }
    if (tid == 0) *out_loss = red[0];
}

// ---------------------------------------------------------------------------
extern "C" void kernel_launch(void* const* d_in, const int* in_sizes, int n_in,
                              void* d_out, int out_size) {
    const float* x     = (const float*)d_in[0];
    const float* embed = (const float*)d_in[1];
    float* out      = (float*)d_out;
    float* out_q    = out;                                   // N*DIM
    float* out_ind  = out + (size_t)N_PTS * DIM;             // N
    float* out_loss = out + (size_t)N_PTS * DIM + N_PTS;     // 1

    const int gemm_smem = 49152 * (int)sizeof(float);                      // 192 KB
    const int smax_smem = (8 * KCODES + KCODES + 8) * (int)sizeof(float);  // ~72 KB
    cudaFuncSetAttribute(gemm_kernel,    cudaFuncAttributeMaxDynamicSharedMemorySize, gemm_smem);
    cudaFuncSetAttribute(softmax_kernel, cudaFuncAttributeMaxDynamicSharedMemorySize, smax_smem);

    prep_kernel   <<<256, 256>>>(embed);
    gemm_kernel   <<<N_PTS / BM, 256, gemm_smem>>>(x, embed, out_q, out_ind);
    softmax_kernel<<<304, 256, smax_smem>>>();
    loss_kernel   <<<1, 256>>>(out_loss);
}

// round 5
// speedup vs baseline: 1.4773x; 1.4773x over previous
#include <cuda_runtime.h>
#include <stdint.h>
#include <math.h>

#define N_PTS   32768
#define KCODES  2048
#define DIM     128
#define BM      128
#define BN      32
#define NTILES  (KCODES / BN)        // 64
#define TEMP_INV (1.0f/0.9f)

// Scratch (allocation-free rule: __device__ globals)
__device__ float g_conf[(size_t)N_PTS * KCODES];   // 256 MB conf' spill
__device__ float g_maxv[N_PTS];
__device__ float g_esq[KCODES];
__device__ float g_clsum[KCODES];
__device__ float g_bhi[KCODES * DIM];              // B hi split, fragment order, tile-major
__device__ float g_blo[KCODES * DIM];              // B lo split, fragment order, tile-major

__device__ __forceinline__ float tf32r(float a) {
    float r;
    asm("cvt.rna.tf32.f32 %0, %1;" : "=f"(r) : "f"(a));
    return r;
}

__device__ __forceinline__ void cp_async16(uint32_t saddr, const void* gptr) {
    asm volatile("cp.async.cg.shared.global [%0], [%1], 16;" :: "r"(saddr), "l"(gptr));
}

#define MMA_TF32(d, a, b) \
    asm volatile("mma.sync.aligned.m16n8k8.row.col.f32.tf32.tf32.f32 " \
        "{%0,%1,%2,%3},{%4,%5,%6,%7},{%8,%9},{%0,%1,%2,%3};" \
        : "+f"((d)[0]), "+f"((d)[1]), "+f"((d)[2]), "+f"((d)[3]) \
        : "r"(__float_as_uint((a)[0])), "r"(__float_as_uint((a)[1])), \
          "r"(__float_as_uint((a)[2])), "r"(__float_as_uint((a)[3])), \
          "r"(__float_as_uint((b)[0])), "r"(__float_as_uint((b)[1])))

// ---------------------------------------------------------------------------
// Kernel 1: e_sq per code (warp per code), zero class accumulators, and
// pre-split embed into tf32 hi/lo in MMA FRAGMENT ORDER, tile-major (BN=32):
//   offset = ct*4096 + (((wn*2+nt)*16 + ks)*32 + gid*4 + j)*2 + slot
//   with n: ct=n>>5, wn=(n>>4)&1, nt=(n>>3)&1, gid=n&7;  k: ks=k4>>1, slot=k4&1
// ---------------------------------------------------------------------------
__global__ void prep_kernel(const float* __restrict__ embed) {
    const int tid  = blockIdx.x * blockDim.x + threadIdx.x;  // 0..65535
    const int lane = tid & 31;
    const int warp = tid >> 5;
    if (tid < KCODES) g_clsum[tid] = 0.f;

    // e_sq
    {
        const float* row = embed + (size_t)warp * DIM;
        float s = 0.f;
        #pragma unroll
        for (int i = 0; i < 4; ++i) { float v = row[lane + 32 * i]; s = fmaf(v, v, s); }
        #pragma unroll
        for (int o = 16; o > 0; o >>= 1) s += __shfl_down_sync(0xffffffffu, s, o);
        if (lane == 0) g_esq[warp] = s;
    }

    // B split: one float4 (4 consecutive k) per thread
    {
        float4 v = ((const float4*)embed)[tid];
        const int n   = tid >> 5;          // code row
        const int k4  = tid & 31;          // float4 index along k
        const int ct  = n >> 5;
        const int wn  = (n >> 4) & 1;
        const int nt  = (n >> 3) & 1;
        const int gid = n & 7;
        const int ks  = k4 >> 1;
        const int slot = k4 & 1;
        float a4[4] = {v.x, v.y, v.z, v.w};
        #pragma unroll
        for (int j = 0; j < 4; ++j) {
            float hi = tf32r(a4[j]);
            float lo = tf32r(a4[j] - hi);
            size_t o = (size_t)ct * 4096 +
                       ((size_t)(((wn * 2 + nt) * 16 + ks) * 32 + gid * 4 + j)) * 2 + slot;
            g_bhi[o] = hi;
            g_blo[o] = lo;
        }
    }
}

// ---------------------------------------------------------------------------
// Kernel 2: 3xTF32 GEMM, fragment-order smem, cp.async double-buffered B.
// smem: a_hi[16384] a_lo[16384] (128KB) + B stages 2 x (hi4096|lo4096) (64KB)
// 8 warps (4m x 2n), warp tile 32x16, K=128 resident, 64 B-tiles of 32 codes.
// ---------------------------------------------------------------------------
__global__ void __launch_bounds__(256, 1)
gemm_kernel(const float* __restrict__ x,
            const float* __restrict__ embed,
            float* __restrict__ out_q,
            float* __restrict__ out_ind) {
    extern __shared__ float sm[];
    float* a_hi = sm;
    float* a_lo = sm + 16384;
    float* b_st = sm + 32768;          // [2][8192]: per stage: hi[4096] lo[4096]

    const int tid  = threadIdx.x;
    const int lane = tid & 31;
    const int w    = tid >> 5;
    const int wm   = w >> 1;          // 0..3: 32-point slab
    const int wn   = w & 1;           // 0..1: 16-code slab
    const int n0   = blockIdx.x * BM;

    const uint32_t b_st_s = (uint32_t)__cvta_generic_to_shared(b_st);

    // ---- issue B tile 0 copy (cp.async, no registers held) ----
    {
        const float4* gh = (const float4*)g_bhi;
        const float4* gl = (const float4*)g_blo;
        #pragma unroll
        for (int i = 0; i < 4; ++i) {
            cp_async16(b_st_s + (i * 256 + tid) * 16,         &gh[i * 256 + tid]);
            cp_async16(b_st_s + 16384 + (i * 256 + tid) * 16, &gl[i * 256 + tid]);
        }
        asm volatile("cp.async.commit_group;");
    }

    // ---- A split (x scaled by 2, exact) directly into fragment order ----
    {
        const float4* x4 = (const float4*)(x + (size_t)n0 * DIM);
        #pragma unroll
        for (int t = 0; t < 16; ++t) {
            int idx = t * 256 + tid;
            int m  = idx >> 5;
            int k4 = idx & 31;
            float4 v = x4[idx];
            float a4[4] = {2.f * v.x, 2.f * v.y, 2.f * v.z, 2.f * v.w};
            int r    = m & 15;
            int base = (((m >> 4) * 16 + (k4 >> 1)) * 32) * 4;
            int sl   = (r >> 3) + ((k4 & 1) << 1);
            #pragma unroll
            for (int j = 0; j < 4; ++j) {
                float hi = tf32r(a4[j]);
                float lo = tf32r(a4[j] - hi);
                int addr = base + ((r & 7) * 4 + j) * 4 + sl;
                a_hi[addr] = hi;
                a_lo[addr] = lo;
            }
        }
    }

    float runv[4];
    int   runi[4];
    #pragma unroll
    for (int i = 0; i < 4; ++i) { runv[i] = -3.0e38f; runi[i] = 0; }

    for (int ct = 0; ct < NTILES; ++ct) {
        // issue next tile into other stage, then wait for current stage
        if (ct + 1 < NTILES) {
            const float4* gh = (const float4*)(g_bhi + (size_t)(ct + 1) * 4096);
            const float4* gl = (const float4*)(g_blo + (size_t)(ct + 1) * 4096);
            uint32_t dst = b_st_s + (uint32_t)(((ct + 1) & 1) * 32768);
            #pragma unroll
            for (int i = 0; i < 4; ++i) {
                cp_async16(dst + (i * 256 + tid) * 16,         &gh[i * 256 + tid]);
                cp_async16(dst + 16384 + (i * 256 + tid) * 16, &gl[i * 256 + tid]);
            }
            asm volatile("cp.async.commit_group;");
            asm volatile("cp.async.wait_group 1;");
        } else {
            asm volatile("cp.async.wait_group 0;");
        }
        __syncthreads();                      // stage (ct&1) visible to all warps

        const float* b_hi = b_st + (ct & 1) * 8192;
        const float* b_lo = b_hi + 4096;

        float acc[2][2][4];
        #pragma unroll
        for (int mt = 0; mt < 2; ++mt)
            #pragma unroll
            for (int nt = 0; nt < 2; ++nt)
                #pragma unroll
                for (int r = 0; r < 4; ++r) acc[mt][nt][r] = 0.f;

        #pragma unroll
        for (int ks = 0; ks < 16; ++ks) {
            float4 ah4[2], al4[2];
            #pragma unroll
            for (int mt = 0; mt < 2; ++mt) {
                int ab = (((wm * 2 + mt) * 16 + ks) * 32 + lane) * 4;
                ah4[mt] = *(const float4*)&a_hi[ab];
                al4[mt] = *(const float4*)&a_lo[ab];
            }
            float2 bh2[2], bl2[2];
            #pragma unroll
            for (int nt = 0; nt < 2; ++nt) {
                int bb = (((wn * 2 + nt) * 16 + ks) * 32 + lane) * 2;
                bh2[nt] = *(const float2*)&b_hi[bb];
                bl2[nt] = *(const float2*)&b_lo[bb];
            }
            #pragma unroll
            for (int mt = 0; mt < 2; ++mt)
                #pragma unroll
                for (int nt = 0; nt < 2; ++nt) {
                    MMA_TF32(acc[mt][nt], (&ah4[mt].x), (&bh2[nt].x));   // hi*hi
                    MMA_TF32(acc[mt][nt], (&ah4[mt].x), (&bl2[nt].x));   // hi*lo
                    MMA_TF32(acc[mt][nt], (&al4[mt].x), (&bh2[nt].x));   // lo*hi
                }
        }

        // ---- epilogue: conf = acc - esq, argmax (ascending code), spill ----
        const int c0 = ct * BN;
        #pragma unroll
        for (int nt = 0; nt < 2; ++nt) {
            int cb = c0 + wn * 16 + nt * 8 + 2 * (lane & 3);
            float e0 = __ldg(&g_esq[cb]);
            float e1 = __ldg(&g_esq[cb + 1]);
            #pragma unroll
            for (int mt = 0; mt < 2; ++mt) {
                #pragma unroll
                for (int h = 0; h < 2; ++h) {
                    int slot = mt * 2 + h;
                    int row  = n0 + wm * 32 + mt * 16 + (lane >> 2) + h * 8;
                    float v0 = acc[mt][nt][2 * h + 0] - e0;
                    float v1 = acc[mt][nt][2 * h + 1] - e1;
                    if (v0 > runv[slot]) { runv[slot] = v0; runi[slot] = cb; }
                    if (v1 > runv[slot]) { runv[slot] = v1; runi[slot] = cb + 1; }
                    *(float2*)&g_conf[(size_t)row * KCODES + cb] = make_float2(v0, v1);
                }
            }
        }
        __syncthreads();                      // all warps done with stage before overwrite
    }

    // ---- cross-thread argmax reduction: 8 contributors per point row ----
    float* red_v = sm;                         // [BM][8]
    int*   red_i = (int*)(sm + BM * 8);        // [BM][8]
    int*   sidx  = (int*)(sm + BM * 16);       // [BM]
    #pragma unroll
    for (int mt = 0; mt < 2; ++mt)
        #pragma unroll
        for (int h = 0; h < 2; ++h) {
            int slot = mt * 2 + h;
            int rloc = wm * 32 + mt * 16 + (lane >> 2) + h * 8;
            int cidx = wn * 4 + (lane & 3);
            red_v[rloc * 8 + cidx] = runv[slot];
            red_i[rloc * 8 + cidx] = runi[slot];
        }
    __syncthreads();
    if (tid < BM) {
        float bv = red_v[tid * 8];
        int   bi = red_i[tid * 8];
        #pragma unroll
        for (int t = 1; t < 8; ++t) {
            float v  = red_v[tid * 8 + t];
            int   ii = red_i[tid * 8 + t];
            if (v > bv || (v == bv && ii < bi)) { bv = v; bi = ii; }
        }
        g_maxv[n0 + tid]  = bv;
        sidx[tid]         = bi;
        out_ind[n0 + tid] = (float)bi;
    }
    __syncthreads();

    // ---- fused gather: one warp copies one 512B codebook row per point ----
    {
        const float4* e4 = (const float4*)embed;
        float4*       q4 = (float4*)out_q;
        for (int p = w; p < BM; p += 8) {
            int idx = sidx[p];
            q4[(size_t)(n0 + p) * 32 + lane] = e4[(size_t)idx * 32 + lane];
        }
    }
}

// ---------------------------------------------------------------------------
// Kernel 3: softmax - persistent blocks, smem class bins, no atomics in loop.
// ---------------------------------------------------------------------------
__global__ void softmax_kernel() {
    extern __shared__ float smem[];
    float* eb   = smem;                        // [8][KCODES]
    float* bins = smem + 8 * KCODES;           // [KCODES]
    float* zinv = bins + KCODES;               // [8]
    const int tid  = threadIdx.x;
    const int lane = tid & 31;
    const int w    = tid >> 5;

    for (int k = tid; k < KCODES; k += 256) bins[k] = 0.f;

    for (int g = blockIdx.x; g < N_PTS / 8; g += gridDim.x) {
        const int n = g * 8 + w;
        const float m = g_maxv[n];
        const float4* row4 = (const float4*)&g_conf[(size_t)n * KCODES];

        float z = 0.f;
        #pragma unroll
        for (int j = 0; j < 16; ++j) {
            int k4 = j * 32 + lane;
            float4 c = row4[k4];
            float4 e;
            e.x = __expf((c.x - m) * TEMP_INV);
            e.y = __expf((c.y - m) * TEMP_INV);
            e.z = __expf((c.z - m) * TEMP_INV);
            e.w = __expf((c.w - m) * TEMP_INV);
            *(float4*)&eb[w * KCODES + k4 * 4] = e;
            z += (e.x + e.y) + (e.z + e.w);
        }
        #pragma unroll
        for (int o = 16; o > 0; o >>= 1) z += __shfl_down_sync(0xffffffffu, z, o);
        if (lane == 0) zinv[w] = 1.f / z;      // z >= 1 (argmax term)
        __syncthreads();

        for (int k = tid; k < KCODES; k += 256) {
            float s = 0.f;
            #pragma unroll
            for (int ww = 0; ww < 8; ++ww) s = fmaf(eb[ww * KCODES + k], zinv[ww], s);
            bins[k] += s;
        }
        __syncthreads();
    }

    for (int k = tid; k < KCODES; k += 256) atomicAdd(&g_clsum[k], bins[k]);
}

// ---------------------------------------------------------------------------
// Kernel 4: diversity loss = sum_k p_k * log(p_k + eps).
// ---------------------------------------------------------------------------
__global__ void loss_kernel(float* __restrict__ out_loss) {
    __shared__ float red[256];
    const int tid = threadIdx.x;
    float acc = 0.f;
    for (int k = tid; k < KCODES; k += 256) {
        float p = g_clsum[k] * (1.0f / (float)N_PTS);
        acc += p * logf(p + 1e-6f);
    }
    red[tid] = acc;
    __syncthreads();
    for (int s = 128; s > 0; s >>= 1) {
        if (tid < s) red[tid] += red[tid + s];
        __syncthreads();
    }
    if (tid == 0) *out_loss = red[0];
}

// ---------------------------------------------------------------------------
extern "C" void kernel_launch(void* const* d_in, const int* in_sizes, int n_in,
                              void* d_out, int out_size) {
    const float* x     = (const float*)d_in[0];
    const float* embed = (const float*)d_in[1];
    float* out      = (float*)d_out;
    float* out_q    = out;                                   // N*DIM
    float* out_ind  = out + (size_t)N_PTS * DIM;             // N
    float* out_loss = out + (size_t)N_PTS * DIM + N_PTS;     // 1

    const int gemm_smem = 49152 * (int)sizeof(float);                      // 192 KB
    const int smax_smem = (8 * KCODES + KCODES + 8) * (int)sizeof(float);  // ~72 KB
    cudaFuncSetAttribute(gemm_kernel,    cudaFuncAttributeMaxDynamicSharedMemorySize, gemm_smem);
    cudaFuncSetAttribute(softmax_kernel, cudaFuncAttributeMaxDynamicSharedMemorySize, smax_smem);

    prep_kernel   <<<256, 256>>>(embed);
    gemm_kernel   <<<N_PTS / BM, 256, gemm_smem>>>(x, embed, out_q, out_ind);
    softmax_kernel<<<304, 256, smax_smem>>>();
    loss_kernel   <<<1, 256>>>(out_loss);
}

// round 6
// speedup vs baseline: 1.4784x; 1.0008x over previous
#include <cuda_runtime.h>
#include <stdint.h>
#include <math.h>

#define N_PTS   32768
#define KCODES  2048
#define DIM     128
#define BM      128
#define BN      32
#define NTILES  (KCODES / BN)        // 64
#define TEMP_INV (1.0f/0.9f)

// Scratch (allocation-free rule: __device__ globals)
__device__ float g_conf[(size_t)N_PTS * KCODES];   // 256 MB conf' spill
__device__ float g_esq[KCODES];
__device__ float g_clsum[KCODES];
__device__ float g_bhi[KCODES * DIM];              // B hi split, fragment order, tile-major
__device__ float g_blo[KCODES * DIM];              // B lo split, fragment order, tile-major

__device__ __forceinline__ float tf32r(float a) {
    float r;
    asm("cvt.rna.tf32.f32 %0, %1;" : "=f"(r) : "f"(a));
    return r;
}

__device__ __forceinline__ void cp_async16(uint32_t saddr, const void* gptr) {
    asm volatile("cp.async.cg.shared.global [%0], [%1], 16;" :: "r"(saddr), "l"(gptr));
}

#define MMA_TF32(d, a, b) \
    asm volatile("mma.sync.aligned.m16n8k8.row.col.f32.tf32.tf32.f32 " \
        "{%0,%1,%2,%3},{%4,%5,%6,%7},{%8,%9},{%0,%1,%2,%3};" \
        : "+f"((d)[0]), "+f"((d)[1]), "+f"((d)[2]), "+f"((d)[3]) \
        : "r"(__float_as_uint((a)[0])), "r"(__float_as_uint((a)[1])), \
          "r"(__float_as_uint((a)[2])), "r"(__float_as_uint((a)[3])), \
          "r"(__float_as_uint((b)[0])), "r"(__float_as_uint((b)[1])))

// ---------------------------------------------------------------------------
// Kernel 1: e_sq per code (warp per code), zero class accumulators, and
// pre-split embed into tf32 hi/lo in MMA FRAGMENT ORDER, tile-major (BN=32).
// ---------------------------------------------------------------------------
__global__ void prep_kernel(const float* __restrict__ embed) {
    const int tid  = blockIdx.x * blockDim.x + threadIdx.x;  // 0..65535
    const int lane = tid & 31;
    const int warp = tid >> 5;
    if (tid < KCODES) g_clsum[tid] = 0.f;

    // e_sq
    {
        const float* row = embed + (size_t)warp * DIM;
        float s = 0.f;
        #pragma unroll
        for (int i = 0; i < 4; ++i) { float v = row[lane + 32 * i]; s = fmaf(v, v, s); }
        #pragma unroll
        for (int o = 16; o > 0; o >>= 1) s += __shfl_down_sync(0xffffffffu, s, o);
        if (lane == 0) g_esq[warp] = s;
    }

    // B split: one float4 (4 consecutive k) per thread
    {
        float4 v = ((const float4*)embed)[tid];
        const int n   = tid >> 5;          // code row
        const int k4  = tid & 31;          // float4 index along k
        const int ct  = n >> 5;
        const int wn  = (n >> 4) & 1;
        const int nt  = (n >> 3) & 1;
        const int gid = n & 7;
        const int ks  = k4 >> 1;
        const int slot = k4 & 1;
        float a4[4] = {v.x, v.y, v.z, v.w};
        #pragma unroll
        for (int j = 0; j < 4; ++j) {
            float hi = tf32r(a4[j]);
            float lo = tf32r(a4[j] - hi);
            size_t o = (size_t)ct * 4096 +
                       ((size_t)(((wn * 2 + nt) * 16 + ks) * 32 + gid * 4 + j)) * 2 + slot;
            g_bhi[o] = hi;
            g_blo[o] = lo;
        }
    }
}

// ---------------------------------------------------------------------------
// Kernel 2: 3xTF32 GEMM + argmax + gather + FUSED per-point softmax & class
// bin accumulation (conf rows re-read while L2-hot).
// ---------------------------------------------------------------------------
__global__ void __launch_bounds__(256, 1)
gemm_kernel(const float* __restrict__ x,
            const float* __restrict__ embed,
            float* __restrict__ out_q,
            float* __restrict__ out_ind) {
    extern __shared__ float sm[];
    float* a_hi = sm;
    float* a_lo = sm + 16384;
    float* b_st = sm + 32768;          // [2][8192]: per stage: hi[4096] lo[4096]

    const int tid  = threadIdx.x;
    const int lane = tid & 31;
    const int w    = tid >> 5;
    const int wm   = w >> 1;          // 0..3: 32-point slab
    const int wn   = w & 1;           // 0..1: 16-code slab
    const int n0   = blockIdx.x * BM;

    const uint32_t b_st_s = (uint32_t)__cvta_generic_to_shared(b_st);

    // ---- issue B tile 0 copy (cp.async, no registers held) ----
    {
        const float4* gh = (const float4*)g_bhi;
        const float4* gl = (const float4*)g_blo;
        #pragma unroll
        for (int i = 0; i < 4; ++i) {
            cp_async16(b_st_s + (i * 256 + tid) * 16,         &gh[i * 256 + tid]);
            cp_async16(b_st_s + 16384 + (i * 256 + tid) * 16, &gl[i * 256 + tid]);
        }
        asm volatile("cp.async.commit_group;");
    }

    // ---- A split (x scaled by 2, exact) directly into fragment order ----
    {
        const float4* x4 = (const float4*)(x + (size_t)n0 * DIM);
        #pragma unroll
        for (int t = 0; t < 16; ++t) {
            int idx = t * 256 + tid;
            int m  = idx >> 5;
            int k4 = idx & 31;
            float4 v = x4[idx];
            float a4[4] = {2.f * v.x, 2.f * v.y, 2.f * v.z, 2.f * v.w};
            int r    = m & 15;
            int base = (((m >> 4) * 16 + (k4 >> 1)) * 32) * 4;
            int sl   = (r >> 3) + ((k4 & 1) << 1);
            #pragma unroll
            for (int j = 0; j < 4; ++j) {
                float hi = tf32r(a4[j]);
                float lo = tf32r(a4[j] - hi);
                int addr = base + ((r & 7) * 4 + j) * 4 + sl;
                a_hi[addr] = hi;
                a_lo[addr] = lo;
            }
        }
    }

    float runv[4];
    int   runi[4];
    #pragma unroll
    for (int i = 0; i < 4; ++i) { runv[i] = -3.0e38f; runi[i] = 0; }

    for (int ct = 0; ct < NTILES; ++ct) {
        // issue next tile into other stage, then wait for current stage
        if (ct + 1 < NTILES) {
            const float4* gh = (const float4*)(g_bhi + (size_t)(ct + 1) * 4096);
            const float4* gl = (const float4*)(g_blo + (size_t)(ct + 1) * 4096);
            uint32_t dst = b_st_s + (uint32_t)(((ct + 1) & 1) * 32768);
            #pragma unroll
            for (int i = 0; i < 4; ++i) {
                cp_async16(dst + (i * 256 + tid) * 16,         &gh[i * 256 + tid]);
                cp_async16(dst + 16384 + (i * 256 + tid) * 16, &gl[i * 256 + tid]);
            }
            asm volatile("cp.async.commit_group;");
            asm volatile("cp.async.wait_group 1;");
        } else {
            asm volatile("cp.async.wait_group 0;");
        }
        __syncthreads();                      // stage (ct&1) visible to all warps

        const float* b_hi = b_st + (ct & 1) * 8192;
        const float* b_lo = b_hi + 4096;

        float acc[2][2][4];
        #pragma unroll
        for (int mt = 0; mt < 2; ++mt)
            #pragma unroll
            for (int nt = 0; nt < 2; ++nt)
                #pragma unroll
                for (int r = 0; r < 4; ++r) acc[mt][nt][r] = 0.f;

        #pragma unroll
        for (int ks = 0; ks < 16; ++ks) {
            float4 ah4[2], al4[2];
            #pragma unroll
            for (int mt = 0; mt < 2; ++mt) {
                int ab = (((wm * 2 + mt) * 16 + ks) * 32 + lane) * 4;
                ah4[mt] = *(const float4*)&a_hi[ab];
                al4[mt] = *(const float4*)&a_lo[ab];
            }
            float2 bh2[2], bl2[2];
            #pragma unroll
            for (int nt = 0; nt < 2; ++nt) {
                int bb = (((wn * 2 + nt) * 16 + ks) * 32 + lane) * 2;
                bh2[nt] = *(const float2*)&b_hi[bb];
                bl2[nt] = *(const float2*)&b_lo[bb];
            }
            #pragma unroll
            for (int mt = 0; mt < 2; ++mt)
                #pragma unroll
                for (int nt = 0; nt < 2; ++nt) {
                    MMA_TF32(acc[mt][nt], (&ah4[mt].x), (&bh2[nt].x));   // hi*hi
                    MMA_TF32(acc[mt][nt], (&ah4[mt].x), (&bl2[nt].x));   // hi*lo
                    MMA_TF32(acc[mt][nt], (&al4[mt].x), (&bh2[nt].x));   // lo*hi
                }
        }

        // ---- epilogue: conf = acc - esq, argmax (ascending code), spill ----
        const int c0 = ct * BN;
        #pragma unroll
        for (int nt = 0; nt < 2; ++nt) {
            int cb = c0 + wn * 16 + nt * 8 + 2 * (lane & 3);
            float e0 = __ldg(&g_esq[cb]);
            float e1 = __ldg(&g_esq[cb + 1]);
            #pragma unroll
            for (int mt = 0; mt < 2; ++mt) {
                #pragma unroll
                for (int h = 0; h < 2; ++h) {
                    int slot = mt * 2 + h;
                    int row  = n0 + wm * 32 + mt * 16 + (lane >> 2) + h * 8;
                    float v0 = acc[mt][nt][2 * h + 0] - e0;
                    float v1 = acc[mt][nt][2 * h + 1] - e1;
                    if (v0 > runv[slot]) { runv[slot] = v0; runi[slot] = cb; }
                    if (v1 > runv[slot]) { runv[slot] = v1; runi[slot] = cb + 1; }
                    *(float2*)&g_conf[(size_t)row * KCODES + cb] = make_float2(v0, v1);
                }
            }
        }
        __syncthreads();                      // all warps done with stage before overwrite
    }

    // ---- cross-thread argmax reduction: 8 contributors per point row ----
    float* red_v  = sm;                         // [BM][8]      floats 0..1023
    int*   red_i  = (int*)(sm + BM * 8);        // [BM][8]      1024..2047
    int*   sidx   = (int*)(sm + BM * 16);       // [BM]         2048..2175
    float* maxv_s = sm + BM * 16 + BM;          // [BM]         2176..2303
    float* bins_s = sm + BM * 18;               // [KCODES]     2304..4351 (disjoint)
    #pragma unroll
    for (int mt = 0; mt < 2; ++mt)
        #pragma unroll
        for (int h = 0; h < 2; ++h) {
            int slot = mt * 2 + h;
            int rloc = wm * 32 + mt * 16 + (lane >> 2) + h * 8;
            int cidx = wn * 4 + (lane & 3);
            red_v[rloc * 8 + cidx] = runv[slot];
            red_i[rloc * 8 + cidx] = runi[slot];
        }
    __syncthreads();
    if (tid < BM) {
        float bv = red_v[tid * 8];
        int   bi = red_i[tid * 8];
        #pragma unroll
        for (int t = 1; t < 8; ++t) {
            float v  = red_v[tid * 8 + t];
            int   ii = red_i[tid * 8 + t];
            if (v > bv || (v == bv && ii < bi)) { bv = v; bi = ii; }
        }
        maxv_s[tid]       = bv;
        sidx[tid]         = bi;
        out_ind[n0 + tid] = (float)bi;
    }
    __syncthreads();

    // ---- fused gather + zero class bins ----
    {
        const float4* e4 = (const float4*)embed;
        float4*       q4 = (float4*)out_q;
        for (int p = w; p < BM; p += 8) {
            int idx = sidx[p];
            q4[(size_t)(n0 + p) * 32 + lane] = e4[(size_t)idx * 32 + lane];
        }
        for (int k = tid; k < KCODES; k += 256) bins_s[k] = 0.f;
    }
    __syncthreads();

    // ---- FUSED softmax: warp w handles points [16w, 16w+16). Each thread
    // owns codes {j*128 + lane*4 + t : j<16, t<4}; bins accumulate in regs. ----
    {
        float bins_r[64];
        #pragma unroll
        for (int i = 0; i < 64; ++i) bins_r[i] = 0.f;

        for (int p = 0; p < 16; ++p) {
            const int pl = w * 16 + p;
            const float m = maxv_s[pl];
            const float4* row4 = (const float4*)&g_conf[(size_t)(n0 + pl) * KCODES];

            float e[64];
            float z = 0.f;
            #pragma unroll
            for (int j = 0; j < 16; ++j) {
                float4 c = row4[j * 32 + lane];
                float e0 = __expf((c.x - m) * TEMP_INV);
                float e1 = __expf((c.y - m) * TEMP_INV);
                float e2 = __expf((c.z - m) * TEMP_INV);
                float e3 = __expf((c.w - m) * TEMP_INV);
                e[j * 4 + 0] = e0; e[j * 4 + 1] = e1;
                e[j * 4 + 2] = e2; e[j * 4 + 3] = e3;
                z += (e0 + e1) + (e2 + e3);
            }
            #pragma unroll
            for (int o = 16; o > 0; o >>= 1) z += __shfl_xor_sync(0xffffffffu, z, o);
            const float zi = 1.f / z;          // z >= 1 (argmax term present)
            #pragma unroll
            for (int i = 0; i < 64; ++i) bins_r[i] = fmaf(e[i], zi, bins_r[i]);
        }

        // flush register bins -> smem bins (block atomics), then -> global
        #pragma unroll
        for (int i = 0; i < 64; ++i) {
            int k = (i >> 2) * 128 + lane * 4 + (i & 3);
            atomicAdd(&bins_s[k], bins_r[i]);
        }
    }
    __syncthreads();
    for (int k = tid; k < KCODES; k += 256) atomicAdd(&g_clsum[k], bins_s[k]);
}

// ---------------------------------------------------------------------------
// Kernel 3: diversity loss = sum_k p_k * log(p_k + eps).
// ---------------------------------------------------------------------------
__global__ void loss_kernel(float* __restrict__ out_loss) {
    __shared__ float red[256];
    const int tid = threadIdx.x;
    float acc = 0.f;
    for (int k = tid; k < KCODES; k += 256) {
        float p = g_clsum[k] * (1.0f / (float)N_PTS);
        acc += p * logf(p + 1e-6f);
    }
    red[tid] = acc;
    __syncthreads();
    for (int s = 128; s > 0; s >>= 1) {
        if (tid < s) red[tid] += red[tid + s];
        __syncthreads();
    }
    if (tid == 0) *out_loss = red[0];
}

// ---------------------------------------------------------------------------
extern "C" void kernel_launch(void* const* d_in, const int* in_sizes, int n_in,
                              void* d_out, int out_size) {
    const float* x     = (const float*)d_in[0];
    const float* embed = (const float*)d_in[1];
    float* out      = (float*)d_out;
    float* out_q    = out;                                   // N*DIM
    float* out_ind  = out + (size_t)N_PTS * DIM;             // N
    float* out_loss = out + (size_t)N_PTS * DIM + N_PTS;     // 1

    const int gemm_smem = 49152 * (int)sizeof(float);        // 192 KB
    cudaFuncSetAttribute(gemm_kernel, cudaFuncAttributeMaxDynamicSharedMemorySize, gemm_smem);

    prep_kernel <<<256, 256>>>(embed);
    gemm_kernel <<<N_PTS / BM, 256, gemm_smem>>>(x, embed, out_q, out_ind);
    loss_kernel <<<1, 256>>>(out_loss);
}